// round 3
// baseline (speedup 1.0000x reference)
#include <cuda_runtime.h>
#include <cuda_bf16.h>
#include <cstdint>

// GaussianSplatting preprocess, bandwidth-optimized v3:
//   out = concat(positions[N,3], cov[N,3,3], alphas[N], sh[N,4]) flattened.
//   cov = R (S S^T) R^T per point; sh = [C0, c1*C1, c0*C1, c2*C1].
// v3: cp.async.cg staging (bypass L1 + register round trip) and streaming
// load/store hints on the pure-bandwidth paths.

#define SH_C0 0.282095f
#define SH_C1 0.488603f

constexpr int TILE = 256;

__device__ __forceinline__ void cp_async16(void* smem_dst, const void* gmem_src) {
    uint32_t s = (uint32_t)__cvta_generic_to_shared(smem_dst);
    asm volatile("cp.async.cg.shared.global [%0], [%1], 16;\n" :: "r"(s), "l"(gmem_src));
}

__global__ void __launch_bounds__(TILE) gs_preprocess_kernel(
    const float* __restrict__ positions,  // [N,3]
    const float* __restrict__ colors,     // [N,3]
    const float* __restrict__ alphas,     // [N]
    const float* __restrict__ R,          // [N,3,3]
    const float* __restrict__ S,          // [N,3,3]
    float* __restrict__ out,              // [17N]
    int n)
{
    __shared__ float sh_col[TILE * 3];
    __shared__ float sh_R[TILE * 9];
    __shared__ float sh_S[TILE * 9];   // reused as cov staging buffer

    const int tid = threadIdx.x;
    const int block0 = blockIdx.x * TILE;

    float* __restrict__ out_cov   = out + 3LL * n;
    float* __restrict__ out_alpha = out + 12LL * n;
    float* __restrict__ out_sh    = out + 13LL * n;

    const int cnt = min(TILE, n - block0);   // block0 < n always (grid sized to n)
    const bool full = (cnt == TILE);

    // ---------------- stage colors, R, S into smem ----------------
    if (full) {
        // cp.async 16B chunks, fully coalesced, L1-bypassing.
        const float* cbase = colors + (long long)block0 * 3;   // 192 x 16B
        const float* rbase = R      + (long long)block0 * 9;   // 576 x 16B
        const float* sbase = S      + (long long)block0 * 9;   // 576 x 16B
        if (tid < TILE * 3 / 4)
            cp_async16(sh_col + tid * 4, cbase + tid * 4);
        #pragma unroll
        for (int idx = tid; idx < TILE * 9 / 4; idx += TILE) {
            cp_async16(sh_R + idx * 4, rbase + idx * 4);
            cp_async16(sh_S + idx * 4, sbase + idx * 4);
        }
        asm volatile("cp.async.commit_group;\n");
        asm volatile("cp.async.wait_group 0;\n");
    } else {
        for (int idx = tid; idx < cnt * 3; idx += TILE)
            sh_col[idx] = colors[(long long)block0 * 3 + idx];
        for (int idx = tid; idx < cnt * 9; idx += TILE)
            sh_R[idx] = R[(long long)block0 * 9 + idx];
        for (int idx = tid; idx < cnt * 9; idx += TILE)
            sh_S[idx] = S[(long long)block0 * 9 + idx];
    }
    __syncthreads();

    // ---------------- per-point math ----------------
    if (tid < cnt) {
        const long long i = block0 + tid;

        // ---- SH coeffs ----
        const float c0 = sh_col[tid * 3 + 0];
        const float c1 = sh_col[tid * 3 + 1];
        const float c2 = sh_col[tid * 3 + 2];
        if ((n & 3) == 0) {
            __stcs((float4*)out_sh + i,
                   make_float4(SH_C0, c1 * SH_C1, c0 * SH_C1, c2 * SH_C1));
        } else {
            out_sh[4 * i + 0] = SH_C0;
            out_sh[4 * i + 1] = c1 * SH_C1;
            out_sh[4 * i + 2] = c0 * SH_C1;
            out_sh[4 * i + 3] = c2 * SH_C1;
        }

        // ---- load r, s from smem (stride 9 -> conflict-free) ----
        float r[9], s[9];
        #pragma unroll
        for (int k = 0; k < 9; ++k) r[k] = sh_R[tid * 9 + k];
        #pragma unroll
        for (int k = 0; k < 9; ++k) s[k] = sh_S[tid * 9 + k];

        // ---- M = S S^T (symmetric) ----
        const float m00 = s[0]*s[0] + s[1]*s[1] + s[2]*s[2];
        const float m01 = s[0]*s[3] + s[1]*s[4] + s[2]*s[5];
        const float m02 = s[0]*s[6] + s[1]*s[7] + s[2]*s[8];
        const float m11 = s[3]*s[3] + s[4]*s[4] + s[5]*s[5];
        const float m12 = s[3]*s[6] + s[4]*s[7] + s[5]*s[8];
        const float m22 = s[6]*s[6] + s[7]*s[7] + s[8]*s[8];

        // ---- T = R*M, cov = T*R^T; write into sh_S (own region only) ----
        float t[9];
        #pragma unroll
        for (int a = 0; a < 3; ++a) {
            const float ra0 = r[3*a + 0];
            const float ra1 = r[3*a + 1];
            const float ra2 = r[3*a + 2];
            t[3*a + 0] = ra0*m00 + ra1*m01 + ra2*m02;
            t[3*a + 1] = ra0*m01 + ra1*m11 + ra2*m12;
            t[3*a + 2] = ra0*m02 + ra1*m12 + ra2*m22;
        }
        #pragma unroll
        for (int a = 0; a < 3; ++a)
            #pragma unroll
            for (int l = 0; l < 3; ++l)
                sh_S[tid * 9 + 3*a + l] =
                    t[3*a + 0]*r[3*l + 0] + t[3*a + 1]*r[3*l + 1] + t[3*a + 2]*r[3*l + 2];
    }
    __syncthreads();

    // ---- coalesced cov store (base 3n + blk*9 floats; aligned iff n%4==0) ----
    if (full && (n & 3) == 0) {
        float4* o4 = (float4*)(out_cov + (long long)block0 * 9);
        const float4* shs4 = (const float4*)sh_S;
        #pragma unroll
        for (int idx = tid; idx < TILE * 9 / 4; idx += TILE)
            __stcs(o4 + idx, shs4[idx]);
    } else {
        for (int idx = tid; idx < cnt * 9; idx += TILE)
            out_cov[(long long)block0 * 9 + idx] = sh_S[idx];
    }

    // ---------------- flat passthrough copies (positions, alphas) ----------------
    const long long gtid    = (long long)blockIdx.x * TILE + tid;
    const long long gstride = (long long)gridDim.x * TILE;

    // positions: 3N floats
    {
        const long long nv = (3LL * n) >> 2;
        const float4* p4 = (const float4*)positions;
        float4* o4 = (float4*)out;
        for (long long idx = gtid; idx < nv; idx += gstride)
            __stcs(o4 + idx, __ldcs(p4 + idx));
        for (long long idx = nv * 4 + gtid; idx < 3LL * n; idx += gstride)
            out[idx] = positions[idx];
    }
    // alphas: N floats (dst base 48n B -> always 16B aligned)
    {
        const long long nv = (long long)n >> 2;
        const float4* a4 = (const float4*)alphas;
        float4* o4 = (float4*)out_alpha;
        for (long long idx = gtid; idx < nv; idx += gstride)
            __stcs(o4 + idx, __ldcs(a4 + idx));
        for (long long idx = nv * 4 + gtid; idx < n; idx += gstride)
            out_alpha[idx] = alphas[idx];
    }
}

extern "C" void kernel_launch(void* const* d_in, const int* in_sizes, int n_in,
                              void* d_out, int out_size)
{
    const float* positions = (const float*)d_in[0];
    const float* colors    = (const float*)d_in[1];
    const float* alphas    = (const float*)d_in[2];
    const float* R         = (const float*)d_in[3];
    const float* S         = (const float*)d_in[4];
    float* out = (float*)d_out;

    const int n = in_sizes[2];  // alphas count == N

    const int blocks = (n + TILE - 1) / TILE;
    gs_preprocess_kernel<<<blocks, TILE>>>(positions, colors, alphas, R, S, out, n);
}